// round 2
// baseline (speedup 1.0000x reference)
#include <cuda_runtime.h>
#include <math_constants.h>

// Problem constants
#define NROWS 65536
#define DIN   64
#define NC    1024
#define DOUT  256

// Tiling
#define BM      64     // rows per CTA
#define BK      32     // centers per chunk
#define THREADS 256
#define SROW    68     // padded smem row stride (17 * 16B -> float4-aligned, conflict-free)
#define LOG2E   1.4426950408889634f

struct Smem {
    float xs[BM][SROW];   // 2 * x * s   (fold factor 2 and scale s into x)
    float cs[BK][SROW];   // raw centers chunk
    float pt[BK][SROW];   // P^T: pt[k][row] = softmax numerator
    float vs[BK][DOUT];   // values chunk
    float xsq[BM];        // sum_d x^2 * s
    float csq[BK];        // sum_d c^2 * s
    float s[DIN];
};

__global__ void __launch_bounds__(THREADS, 2)
attnn_fused_kernel(const float* __restrict__ x,
                   const float* __restrict__ ctrs,
                   const float* __restrict__ values,
                   const float* __restrict__ s_in,
                   float* __restrict__ out)
{
    extern __shared__ char smem_raw[];
    Smem& sm = *reinterpret_cast<Smem*>(smem_raw);

    const int tid = threadIdx.x;
    const int ty  = tid >> 4;       // 0..15 : row group (4 rows each)
    const int tx  = tid & 15;       // 0..15 : column/k group
    const int n0  = blockIdx.x * BM;
    const int r0  = ty * 4;

    // ---- load s ----
    if (tid < DIN) sm.s[tid] = s_in[tid];
    __syncthreads();

    // ---- load x tile: xs = 2*x*s, xsq = sum x^2 s ----
    {
        const int r  = tid >> 2;            // 0..63
        const int d0 = (tid & 3) * 16;      // 0,16,32,48
        const float* xrow = x + (size_t)(n0 + r) * DIN + d0;
        float part = 0.f;
        #pragma unroll
        for (int m = 0; m < 16; m += 4) {
            float4 xv = *reinterpret_cast<const float4*>(xrow + m);
            float s0 = sm.s[d0 + m + 0], s1 = sm.s[d0 + m + 1];
            float s2 = sm.s[d0 + m + 2], s3 = sm.s[d0 + m + 3];
            part += xv.x * xv.x * s0 + xv.y * xv.y * s1
                  + xv.z * xv.z * s2 + xv.w * xv.w * s3;
            float4 t = make_float4(2.f * xv.x * s0, 2.f * xv.y * s1,
                                   2.f * xv.z * s2, 2.f * xv.w * s3);
            *reinterpret_cast<float4*>(&sm.xs[r][d0 + m]) = t;
        }
        part += __shfl_xor_sync(0xffffffffu, part, 2);
        part += __shfl_xor_sync(0xffffffffu, part, 1);
        if ((tid & 3) == 0) sm.xsq[r] = part;
    }
    // visibility guaranteed by the first __syncthreads in the main loop

    float acc[4][16];
    #pragma unroll
    for (int i = 0; i < 4; i++)
        #pragma unroll
        for (int c = 0; c < 16; c++) acc[i][c] = 0.f;
    float mrow[4], srow[4];
    #pragma unroll
    for (int i = 0; i < 4; i++) { mrow[i] = -CUDART_INF_F; srow[i] = 0.f; }

    for (int kc = 0; kc < NC; kc += BK) {
        // ---- load centers chunk + csq ----
        {
            const int kk = tid >> 3;            // 0..31
            const int d0 = (tid & 7) * 8;       // 0..56
            const float* crow = ctrs + (size_t)(kc + kk) * DIN + d0;
            float part = 0.f;
            #pragma unroll
            for (int m = 0; m < 8; m += 4) {
                float4 cv = *reinterpret_cast<const float4*>(crow + m);
                part += cv.x * cv.x * sm.s[d0 + m + 0] + cv.y * cv.y * sm.s[d0 + m + 1]
                      + cv.z * cv.z * sm.s[d0 + m + 2] + cv.w * cv.w * sm.s[d0 + m + 3];
                *reinterpret_cast<float4*>(&sm.cs[kk][d0 + m]) = cv;
            }
            part += __shfl_xor_sync(0xffffffffu, part, 4);
            part += __shfl_xor_sync(0xffffffffu, part, 2);
            part += __shfl_xor_sync(0xffffffffu, part, 1);
            if ((tid & 7) == 0) sm.csq[kk] = part;
        }
        // ---- load values chunk (column-interleaved STS to avoid conflicts) ----
        {
            const int kk = tid >> 3;            // 0..31
            const int c0 = (tid & 7) * 4;       // 0..28
            const float* vrow = values + (size_t)(kc + kk) * DOUT;
            #pragma unroll
            for (int q = 0; q < 8; q++) {
                *reinterpret_cast<float4*>(&sm.vs[kk][c0 + 32 * q]) =
                    *reinterpret_cast<const float4*>(vrow + c0 + 32 * q);
            }
        }
        __syncthreads();

        // ---- stage 1: cross terms for 4 rows x 2 centers (k = tx, tx+16) ----
        float cr[4][2];
        #pragma unroll
        for (int i = 0; i < 4; i++) { cr[i][0] = 0.f; cr[i][1] = 0.f; }
        #pragma unroll
        for (int d = 0; d < DIN; d += 4) {
            float4 b0 = *reinterpret_cast<const float4*>(&sm.cs[tx][d]);
            float4 b1 = *reinterpret_cast<const float4*>(&sm.cs[tx + 16][d]);
            #pragma unroll
            for (int i = 0; i < 4; i++) {
                float4 a = *reinterpret_cast<const float4*>(&sm.xs[r0 + i][d]);
                cr[i][0] += a.x * b0.x + a.y * b0.y + a.z * b0.z + a.w * b0.w;
                cr[i][1] += a.x * b1.x + a.y * b1.y + a.z * b1.z + a.w * b1.w;
            }
        }
        const float cq0 = sm.csq[tx];
        const float cq1 = sm.csq[tx + 16];
        float l[4][2];
        #pragma unroll
        for (int i = 0; i < 4; i++) {
            const float xq = sm.xsq[r0 + i];
            // logit (log2 domain) = -(xsq + csq - 2*cross) * log2(e)
            l[i][0] = (cr[i][0] - xq - cq0) * LOG2E;
            l[i][1] = (cr[i][1] - xq - cq1) * LOG2E;
        }

        // ---- stage 2: online softmax update ----
        float cm[4];
        #pragma unroll
        for (int i = 0; i < 4; i++) cm[i] = fmaxf(l[i][0], l[i][1]);
        #pragma unroll
        for (int off = 8; off >= 1; off >>= 1) {
            #pragma unroll
            for (int i = 0; i < 4; i++)
                cm[i] = fmaxf(cm[i], __shfl_xor_sync(0xffffffffu, cm[i], off));
        }
        #pragma unroll
        for (int i = 0; i < 4; i++) {
            const float mn = fmaxf(mrow[i], cm[i]);
            if (mn > mrow[i]) {                 // rescale only when max moved
                const float f = exp2f(mrow[i] - mn);   // exp2f(-inf)=0 on first chunk
                srow[i] *= f;
                #pragma unroll
                for (int c = 0; c < 16; c++) acc[i][c] *= f;
                mrow[i] = mn;
            }
        }
        float p[4][2];
        #pragma unroll
        for (int i = 0; i < 4; i++) {
            p[i][0] = exp2f(l[i][0] - mrow[i]);
            p[i][1] = exp2f(l[i][1] - mrow[i]);
            srow[i] += p[i][0] + p[i][1];
        }
        #pragma unroll
        for (int j = 0; j < 2; j++) {
            float4 pv = make_float4(p[0][j], p[1][j], p[2][j], p[3][j]);
            *reinterpret_cast<float4*>(&sm.pt[tx + 16 * j][r0]) = pv;
        }
        __syncthreads();

        // ---- stage 3: acc += P(64xBK) @ V(BKx256), 4x16 micro-tile ----
        #pragma unroll 4
        for (int k = 0; k < BK; k++) {
            const float4 p4 = *reinterpret_cast<const float4*>(&sm.pt[k][r0]);
            #pragma unroll
            for (int ii = 0; ii < 4; ii++) {
                const float4 v4 =
                    *reinterpret_cast<const float4*>(&sm.vs[k][tx * 4 + 64 * ii]);
                acc[0][ii * 4 + 0] += p4.x * v4.x;
                acc[0][ii * 4 + 1] += p4.x * v4.y;
                acc[0][ii * 4 + 2] += p4.x * v4.z;
                acc[0][ii * 4 + 3] += p4.x * v4.w;
                acc[1][ii * 4 + 0] += p4.y * v4.x;
                acc[1][ii * 4 + 1] += p4.y * v4.y;
                acc[1][ii * 4 + 2] += p4.y * v4.z;
                acc[1][ii * 4 + 3] += p4.y * v4.w;
                acc[2][ii * 4 + 0] += p4.z * v4.x;
                acc[2][ii * 4 + 1] += p4.z * v4.y;
                acc[2][ii * 4 + 2] += p4.z * v4.z;
                acc[2][ii * 4 + 3] += p4.z * v4.w;
                acc[3][ii * 4 + 0] += p4.w * v4.x;
                acc[3][ii * 4 + 1] += p4.w * v4.y;
                acc[3][ii * 4 + 2] += p4.w * v4.z;
                acc[3][ii * 4 + 3] += p4.w * v4.w;
            }
        }
        __syncthreads();   // protect cs/vs/pt before next chunk's loads
    }

    // ---- epilogue: finish row sums, normalize, store ----
    #pragma unroll
    for (int off = 8; off >= 1; off >>= 1) {
        #pragma unroll
        for (int i = 0; i < 4; i++)
            srow[i] += __shfl_xor_sync(0xffffffffu, srow[i], off);
    }
    #pragma unroll
    for (int i = 0; i < 4; i++) {
        const float inv = 1.0f / srow[i];
        float* orow = out + (size_t)(n0 + r0 + i) * DOUT;
        #pragma unroll
        for (int ii = 0; ii < 4; ii++) {
            float4 o = make_float4(acc[i][ii * 4 + 0] * inv,
                                   acc[i][ii * 4 + 1] * inv,
                                   acc[i][ii * 4 + 2] * inv,
                                   acc[i][ii * 4 + 3] * inv);
            *reinterpret_cast<float4*>(orow + tx * 4 + 64 * ii) = o;
        }
    }
}

extern "C" void kernel_launch(void* const* d_in, const int* in_sizes, int n_in,
                              void* d_out, int out_size)
{
    const float* x      = (const float*)d_in[0];   // (65536, 64)
    const float* ctrs   = (const float*)d_in[1];   // (1024, 64)
    const float* values = (const float*)d_in[2];   // (1024, 256)
    const float* s      = (const float*)d_in[3];   // (64,)
    float* out          = (float*)d_out;           // (65536, 256)

    const int smem_bytes = (int)sizeof(Smem);
    cudaFuncSetAttribute(attnn_fused_kernel,
                         cudaFuncAttributeMaxDynamicSharedMemorySize, smem_bytes);
    attnn_fused_kernel<<<NROWS / BM, THREADS, smem_bytes>>>(x, ctrs, values, s, out);
}